// round 13
// baseline (speedup 1.0000x reference)
#include <cuda_runtime.h>

// Problem constants (fixed by the reference): B=8, C=128, H=W=256, L=3, K=5
#define Bn 8
#define Cn 128

// Scratch (static device globals — no allocation in kernel_launch)
__device__ float g_tag0[(size_t)Bn * Cn * 4 * 128 * 128]; // 268 MB
__device__ float g_tag1[(size_t)Bn * Cn * 4 * 64 * 64];   // 67 MB
__device__ float g_tag2[(size_t)Bn * Cn * 4 * 32 * 32];   // 17 MB
__device__ float g_ll1[(size_t)Bn * Cn * 128 * 128];      // 67 MB
__device__ float g_ll2[(size_t)Bn * Cn * 64 * 64];        // 17 MB

// ---------------------------------------------------------------------------
// Forward kernel (one per wavelet level):
//   - computes Haar analysis coefficients for a 36x36 halo'd tile (from the
//     72x72 input region), 4 subbands, into shared memory
//   - writes raw LL (pre-conv) for the next level
//   - depthwise 5x5 conv (SAME) on each subband, scaled by wscale, -> tag
// Block: 256 threads. Tile: 32x32 coefficients. Warp-group f (64 threads)
// handles subband f with 4x4 register blocking per thread.
// ---------------------------------------------------------------------------
template <int LEVEL>
__global__ __launch_bounds__(256) void fwd_kernel(
    const float* __restrict__ x,            // level-0 input (full image)
    const float* __restrict__ wconv_all,    // (L, 4C, 1, 5, 5)
    const float* __restrict__ wscale_all)   // (L, 1, 4C, 1, 1)
{
    constexpr int HC = (LEVEL == 0) ? 128 : ((LEVEL == 1) ? 64 : 32);
    constexpr bool WRITE_LL = (LEVEL < 2);

    __shared__ __align__(16) float sc[4][36][40];
    __shared__ float sw[4][25];
    __shared__ float ss[4];

    const int tid = threadIdx.x;
    const int TPR = HC / 32;
    const int tx = blockIdx.x % TPR, ty = blockIdx.x / TPR;
    const int i0 = ty * 32, j0 = tx * 32;
    const int c = blockIdx.y, b = blockIdx.z;

    const float* wconv  = wconv_all  + (size_t)LEVEL * (4 * Cn) * 25;
    const float* wscale = wscale_all + (size_t)LEVEL * (4 * Cn);

    if (tid < 100) sw[tid / 25][tid % 25] = wconv[(c * 4 + tid / 25) * 25 + tid % 25];
    else if (tid < 104) ss[tid - 100] = wscale[c * 4 + (tid - 100)];

    // Select this level's input plane
    const float* inp;
    if (LEVEL == 0)      inp = x     + (size_t)(b * Cn + c) * (4 * HC * HC);
    else if (LEVEL == 1) inp = g_ll1 + (size_t)(b * Cn + c) * (4 * HC * HC);
    else                 inp = g_ll2 + (size_t)(b * Cn + c) * (4 * HC * HC);

    float* tag = (LEVEL == 0) ? g_tag0 : ((LEVEL == 1) ? g_tag1 : g_tag2);
    float* llp = nullptr;
    if (WRITE_LL) {
        float* llbuf = (LEVEL == 0) ? g_ll1 : g_ll2;
        llp = llbuf + (size_t)(b * Cn + c) * HC * HC;
    }

    // Stage 1: Haar coefficients (with conv zero-padding halo of 2) into smem
    for (int idx = tid; idx < 36 * 36; idx += 256) {
        int ci = idx / 36, cj = idx % 36;
        int gi = i0 - 2 + ci, gj = j0 - 2 + cj;
        float x00 = 0.f, x01 = 0.f, x10 = 0.f, x11 = 0.f;
        if ((unsigned)gi < (unsigned)HC && (unsigned)gj < (unsigned)HC) {
            const float* p = inp + (size_t)(2 * gi) * (2 * HC) + 2 * gj;
            float2 a  = *(const float2*)p;
            float2 bb = *(const float2*)(p + 2 * HC);
            x00 = a.x; x01 = a.y; x10 = bb.x; x11 = bb.y;
        }
        float pa = x00 + x01, pb = x10 + x11;
        float pc = x00 - x01, pd = x10 - x11;
        float ll = 0.5f * (pa + pb);
        sc[0][ci][cj] = ll;                // LL  (lo_h, lo_w)
        sc[1][ci][cj] = 0.5f * (pa - pb);  // f1  (hi_h, lo_w)
        sc[2][ci][cj] = 0.5f * (pc + pd);  // f2  (lo_h, hi_w)
        sc[3][ci][cj] = 0.5f * (pc - pd);  // f3  (hi_h, hi_w)
        if (WRITE_LL && ci >= 2 && ci < 34 && cj >= 2 && cj < 34)
            llp[(size_t)gi * HC + gj] = ll;
    }
    __syncthreads();

    // Stage 2: depthwise 5x5 conv; warp-group f handles subband f
    const int f = tid >> 6;
    const int u = tid & 63;
    const int bi = u >> 3, bj = u & 7;  // 8x8 thread blocks of 4x4 outputs

    float wreg[25];
#pragma unroll
    for (int k = 0; k < 25; ++k) wreg[k] = sw[f][k];

    float acc[4][4];
#pragma unroll
    for (int a = 0; a < 4; ++a)
#pragma unroll
        for (int d = 0; d < 4; ++d) acc[a][d] = 0.f;

#pragma unroll
    for (int r = 0; r < 8; ++r) {
        float rv[8];
        float4 v0 = *(const float4*)&sc[f][4 * bi + r][4 * bj];
        float4 v1 = *(const float4*)&sc[f][4 * bi + r][4 * bj + 4];
        rv[0] = v0.x; rv[1] = v0.y; rv[2] = v0.z; rv[3] = v0.w;
        rv[4] = v1.x; rv[5] = v1.y; rv[6] = v1.z; rv[7] = v1.w;
#pragma unroll
        for (int di = 0; di < 5; ++di) {
            int oi = r - di;
            if (oi >= 0 && oi < 4) {
#pragma unroll
                for (int dj = 0; dj < 5; ++dj) {
                    float wv = wreg[di * 5 + dj];
#pragma unroll
                    for (int cj = 0; cj < 4; ++cj)
                        acc[oi][cj] = fmaf(rv[cj + dj], wv, acc[oi][cj]);
                }
            }
        }
    }

    float s = ss[f];
    float* tp = tag + ((size_t)((b * Cn + c) * 4 + f)) * HC * HC;
#pragma unroll
    for (int oi = 0; oi < 4; ++oi) {
        float4 v = make_float4(acc[oi][0] * s, acc[oi][1] * s,
                               acc[oi][2] * s, acc[oi][3] * s);
        *(float4*)&tp[(size_t)(i0 + 4 * bi + oi) * HC + (j0 + 4 * bj)] = v;
    }
}

// ---------------------------------------------------------------------------
// Final kernel: base depthwise 5x5 conv on x (smem tile) + fused 3-level
// inverse Haar reconstruction (pointwise gathers from tag0/tag1/tag2).
// Block: 256 threads, 32x32 output tile, 2x2 outputs per thread.
// ---------------------------------------------------------------------------
__global__ __launch_bounds__(256) void final_kernel(
    const float* __restrict__ x,
    const float* __restrict__ base_w,      // (C,1,5,5)
    const float* __restrict__ base_b,      // (C,)
    const float* __restrict__ base_scale,  // (1,C,1,1)
    float* __restrict__ out)
{
    __shared__ __align__(16) float sx[36][40];
    __shared__ float swt[25];

    const int tid = threadIdx.x;
    const int tx = blockIdx.x & 7, ty = blockIdx.x >> 3;  // 8x8 tiles of 32
    const int p0 = ty * 32, q0 = tx * 32;
    const int c = blockIdx.y, b = blockIdx.z;

    if (tid < 25) swt[tid] = base_w[c * 25 + tid];

    const float* xp = x + (size_t)(b * Cn + c) * 256 * 256;
    for (int idx = tid; idx < 36 * 36; idx += 256) {
        int ri = idx / 36, rj = idx % 36;
        int gi = p0 - 2 + ri, gj = q0 - 2 + rj;
        float v = 0.f;
        if ((unsigned)gi < 256u && (unsigned)gj < 256u)
            v = __ldg(xp + (size_t)gi * 256 + gj);
        sx[ri][rj] = v;
    }
    __syncthreads();

    const int bi = tid >> 4, bj = tid & 15;  // 16x16 blocks of 2x2 outputs

    // Base conv, 2x2 outputs
    float a00 = 0.f, a01 = 0.f, a10 = 0.f, a11 = 0.f;
#pragma unroll
    for (int r = 0; r < 6; ++r) {
        float rv[6];
#pragma unroll
        for (int k = 0; k < 3; ++k) {
            float2 t = *(const float2*)&sx[2 * bi + r][2 * bj + 2 * k];
            rv[2 * k] = t.x; rv[2 * k + 1] = t.y;
        }
#pragma unroll
        for (int di = 0; di < 5; ++di) {
            int oi = r - di;
            if (oi == 0) {
#pragma unroll
                for (int dj = 0; dj < 5; ++dj) {
                    float wv = swt[di * 5 + dj];
                    a00 = fmaf(rv[dj], wv, a00);
                    a01 = fmaf(rv[dj + 1], wv, a01);
                }
            } else if (oi == 1) {
#pragma unroll
                for (int dj = 0; dj < 5; ++dj) {
                    float wv = swt[di * 5 + dj];
                    a10 = fmaf(rv[dj], wv, a10);
                    a11 = fmaf(rv[dj + 1], wv, a11);
                }
            }
        }
    }

    // Fused 3-level inverse Haar reconstruction
    const int i  = (p0 >> 1) + bi, j  = (q0 >> 1) + bj;  // tag0 grid (128)
    const int i1 = i >> 1,        j1 = j >> 1;           // tag1 grid (64)
    const int i2 = i1 >> 1,       j2 = j1 >> 1;          // tag2 grid (32)

    const size_t bc4 = (size_t)(b * Cn + c) * 4;
    const float* t0 = g_tag0 + bc4 * (128 * 128);
    const float* t1 = g_tag1 + bc4 * (64 * 64);
    const float* t2 = g_tag2 + bc4 * (32 * 32);
    const int P0 = 128 * 128, P1 = 64 * 64, P2 = 32 * 32;
    const int o0 = i * 128 + j, o1 = i1 * 64 + j1, o2 = i2 * 32 + j2;

    float u0 = t0[o0], u1 = t0[P0 + o0], u2 = t0[2 * P0 + o0], u3 = t0[3 * P0 + o0];
    float v0 = t1[o1], v1 = t1[P1 + o1], v2 = t1[2 * P1 + o1], v3 = t1[3 * P1 + o1];
    float w0 = t2[o2], w1 = t2[P2 + o2], w2 = t2[2 * P2 + o2], w3 = t2[3 * P2 + o2];

    float sA = (i1 & 1) ? -1.f : 1.f;
    float sB = (j1 & 1) ? -1.f : 1.f;
    float nll2 = 0.5f * (w0 + sA * w1 + sB * w2 + sA * sB * w3);

    float sC = (i & 1) ? -1.f : 1.f;
    float sD = (j & 1) ? -1.f : 1.f;
    float nll1 = 0.5f * ((v0 + nll2) + sC * v1 + sD * v2 + sC * sD * v3);

    float y0 = u0 + nll1;
    float r00 = 0.5f * (y0 + u1 + u2 + u3);
    float r01 = 0.5f * (y0 + u1 - u2 - u3);
    float r10 = 0.5f * (y0 - u1 + u2 - u3);
    float r11 = 0.5f * (y0 - u1 - u2 + u3);

    float bsc = __ldg(base_scale + c);
    float bbv = __ldg(base_b + c);

    float* op = out + (size_t)(b * Cn + c) * 256 * 256;
    const int p = p0 + 2 * bi, q = q0 + 2 * bj;
    float2 r0 = make_float2(bsc * (a00 + bbv) + r00, bsc * (a01 + bbv) + r01);
    float2 r1 = make_float2(bsc * (a10 + bbv) + r10, bsc * (a11 + bbv) + r11);
    *(float2*)&op[(size_t)p * 256 + q]       = r0;
    *(float2*)&op[(size_t)(p + 1) * 256 + q] = r1;
}

// ---------------------------------------------------------------------------
// kernel_launch: 4 launches, same stream, graph-capturable, no allocations,
// no non-launch CUDA API calls.
// Input order (metadata): x, wt_filter, iwt_filter, base_w, base_b,
//                         base_scale, wconv_w, wscale
// Haar filters are the fixed orthonormal constants (products = 0.5), inlined.
// ---------------------------------------------------------------------------
extern "C" void kernel_launch(void* const* d_in, const int* in_sizes, int n_in,
                              void* d_out, int out_size) {
    (void)in_sizes; (void)n_in; (void)out_size;
    const float* x          = (const float*)d_in[0];
    const float* base_w     = (const float*)d_in[3];
    const float* base_b     = (const float*)d_in[4];
    const float* base_scale = (const float*)d_in[5];
    const float* wconv_w    = (const float*)d_in[6];
    const float* wscale     = (const float*)d_in[7];
    float* out = (float*)d_out;

    fwd_kernel<0><<<dim3(16, Cn, Bn), 256>>>(x, wconv_w, wscale);
    fwd_kernel<1><<<dim3(4,  Cn, Bn), 256>>>(x, wconv_w, wscale);
    fwd_kernel<2><<<dim3(1,  Cn, Bn), 256>>>(x, wconv_w, wscale);
    final_kernel<<<dim3(64, Cn, Bn), 256>>>(x, base_w, base_b, base_scale, out);
}